// round 8
// baseline (speedup 1.0000x reference)
#include <cuda_runtime.h>
#include <math.h>

// ---------------------------------------------------------------------------
// Sizes
// ---------------------------------------------------------------------------
namespace {
constexpr int TOK  = 65536;
constexpr int DIN  = 512;
constexpr int NH   = 4;
constexpr int HD   = 128;
constexpr int HD2  = 256;
constexpr int NAC  = 8;
constexpr int TM   = 64;      // tokens per block
constexpr int NTHR = 256;     // 8 warps
constexpr float EPSV = 1e-5f;

// K1 smem layout (floats). Activation strides == 4 (mod 32); weight-stage
// strides == 8 (mod 32) for conflict-free mma fragment LDS.
constexpr int SXN   = 516;    // xn A operand stride
constexpr int SACT  = 260;    // gemm1 out / gelu act stride
constexpr int SST   = 132;    // state / dy stride
constexpr int SW1   = 264;    // G1 weight stage stride (N=256)
constexpr int SWD   = 136;    // G2/dyn weight stage stride (N=128)
constexpr int SM1_XN   = 0;                     // 64*516 = 33024
constexpr int SM1_WORK = 33024;                 // 16896 floats (aliased uses)
constexpr int SM1_DY   = SM1_WORK + TM * SST;   // dy region = WORK + 8448
constexpr int SM1_WST  = SM1_WORK + 16896;      // 32*136 = 4352
constexpr int SMEM1_FLOATS = SM1_WST + 4352;    // 54272
constexpr int SMEM1_BYTES  = SMEM1_FLOATS * 4;  // 217088

// K2 smem layout
constexpr int SO    = 516;    // A stride
constexpr int SWO   = 520;    // weight stage stride (N=512)
constexpr int SM2_A    = 0;                     // 64*516 = 33024
constexpr int SM2_WST  = 33024;                 // 32*520 = 16640
constexpr int SM2_STAT = SM2_WST + 16640;       // 64 float2 = 128 floats
constexpr int SMEM2_FLOATS = SM2_STAT + 128;    // 49792
constexpr int SMEM2_BYTES  = SMEM2_FLOATS * 4;  // 199168
}

// 128 MB scratch for concatenated head outputs (device global: alloc-free)
__device__ float g_comb[(size_t)TOK * DIN];

// ---------------------------------------------------------------------------
// Helpers
// ---------------------------------------------------------------------------
__device__ __forceinline__ float warp_sum(float v) {
    v += __shfl_xor_sync(0xffffffffu, v, 16);
    v += __shfl_xor_sync(0xffffffffu, v, 8);
    v += __shfl_xor_sync(0xffffffffu, v, 4);
    v += __shfl_xor_sync(0xffffffffu, v, 2);
    v += __shfl_xor_sync(0xffffffffu, v, 1);
    return v;
}

__device__ __forceinline__ float gelu_exact(float u) {
    return 0.5f * u * (1.0f + erff(u * 0.70710678118654752f));
}

// round-to-nearest tf32, returned as float bit pattern
__device__ __forceinline__ float tf32f(float f) {
    unsigned u;
    asm("cvt.rna.tf32.f32 %0, %1;" : "=r"(u) : "f"(f));
    return __uint_as_float(u);
}

__device__ __forceinline__ void mma_tf32(float* c,
                                         unsigned a0, unsigned a1, unsigned a2, unsigned a3,
                                         unsigned b0, unsigned b1) {
    asm volatile(
        "mma.sync.aligned.m16n8k8.row.col.f32.tf32.tf32.f32 "
        "{%0,%1,%2,%3}, {%4,%5,%6,%7}, {%8,%9}, {%0,%1,%2,%3};"
        : "+f"(c[0]), "+f"(c[1]), "+f"(c[2]), "+f"(c[3])
        : "r"(a0), "r"(a1), "r"(a2), "r"(a3), "r"(b0), "r"(b1));
}

// Block-cooperative GEMM: C[64][N] += A[64][K] * W[K][N].
// A in smem (tf32-ready), W staged from global in KT-row tiles (tf32-converted).
// Each warp computes m64 x (NF*8) cols: warp w covers cols [w*NF*8, ...).
// acc layout: acc[(mt*NF + nf)*4 + {0..3}]
template<int NF, int KT>
__device__ __forceinline__ void gemm_block(
    const float* __restrict__ sA, int SA,
    const float* __restrict__ Wg, int N, int K,
    float* __restrict__ sWst, int SW,
    float* __restrict__ acc)
{
    const int tid  = threadIdx.x;
    const int lane = tid & 31;
    const int warp = tid >> 5;
    const int g    = lane >> 2;
    const int tig  = lane & 3;
    const int n0   = warp * (NF * 8);
    const unsigned* uA = (const unsigned*)sA;
    const unsigned* uW = (const unsigned*)sWst;
    const int nf4 = N / 4;

    for (int kt = 0; kt < K; kt += KT) {
        __syncthreads();
        // stage KT x N weight tile, tf32-truncated
        for (int idx = tid; idx < KT * nf4; idx += NTHR) {
            int r = idx / nf4, c = idx % nf4;
            float4 v = *(const float4*)(Wg + (long)(kt + r) * N + c * 4);
            float4 t;
            t.x = tf32f(v.x); t.y = tf32f(v.y); t.z = tf32f(v.z); t.w = tf32f(v.w);
            *(float4*)(sWst + r * SW + c * 4) = t;
        }
        __syncthreads();
        #pragma unroll
        for (int k8 = 0; k8 < KT; k8 += 8) {
            unsigned a[4][4];
            #pragma unroll
            for (int mt = 0; mt < 4; mt++) {
                int rb = mt * 16;
                a[mt][0] = uA[(rb + g)     * SA + kt + k8 + tig];
                a[mt][1] = uA[(rb + g + 8) * SA + kt + k8 + tig];
                a[mt][2] = uA[(rb + g)     * SA + kt + k8 + tig + 4];
                a[mt][3] = uA[(rb + g + 8) * SA + kt + k8 + tig + 4];
            }
            #pragma unroll
            for (int nf = 0; nf < NF; nf++) {
                unsigned b0 = uW[(k8 + tig)     * SW + n0 + nf * 8 + g];
                unsigned b1 = uW[(k8 + tig + 4) * SW + n0 + nf * 8 + g];
                #pragma unroll
                for (int mt = 0; mt < 4; mt++)
                    mma_tf32(acc + (mt * NF + nf) * 4,
                             a[mt][0], a[mt][1], a[mt][2], a[mt][3], b0, b1);
            }
        }
    }
}

extern __shared__ float smem[];

// ---------------------------------------------------------------------------
// K1: LN -> per-head MLP (mma) -> attractor/gate glue -> g_comb
// ---------------------------------------------------------------------------
__global__ void __launch_bounds__(NTHR, 1)
k1_heads(const float* __restrict__ x,
         const float* __restrict__ norm_g, const float* __restrict__ norm_b,
         const float* __restrict__ hW1,    const float* __restrict__ hb1,
         const float* __restrict__ hln_g,  const float* __restrict__ hln_b,
         const float* __restrict__ hW2,    const float* __restrict__ hb2,
         const float* __restrict__ attractors, const float* __restrict__ dynamics,
         const float* __restrict__ gW,     const float* __restrict__ gb)
{
    float* sXN   = smem + SM1_XN;
    float* sWORK = smem + SM1_WORK;   // strides 264 (stage) / 260 (act) / 132 (state)
    float* sDY   = smem + SM1_DY;     // stride 132
    float* sWST  = smem + SM1_WST;

    const int tid  = threadIdx.x;
    const int lane = tid & 31;
    const int warp = tid >> 5;
    const int g    = lane >> 2;
    const int tig  = lane & 3;
    const long t0  = (long)blockIdx.x * TM;

    // ---- phase 0: fp32 LN of x, store tf32-truncated xn -------------------
    for (int i = 0; i < 8; i++) {
        int r = warp * 8 + i;
        const float* xr = x + (t0 + r) * DIN;
        float v[16]; float s = 0.f, ss = 0.f;
        #pragma unroll
        for (int j = 0; j < 16; j++) {
            v[j] = xr[lane + 32 * j];
            s += v[j]; ss += v[j] * v[j];
        }
        s = warp_sum(s); ss = warp_sum(ss);
        float mean = s * (1.f / DIN);
        float rstd = rsqrtf(ss * (1.f / DIN) - mean * mean + EPSV);
        #pragma unroll
        for (int j = 0; j < 16; j++) {
            int c = lane + 32 * j;
            float xn = (v[j] - mean) * rstd * norm_g[c] + norm_b[c];
            sXN[r * SXN + c] = tf32f(xn);
        }
    }
    __syncthreads();

    for (int h = 0; h < NH; h++) {
        // ---- GEMM1: xn[64,512] @ hW1[h][512,256] ---------------------------
        float acc1[64];
        #pragma unroll
        for (int q = 0; q < 64; q++) acc1[q] = 0.f;
        gemm_block<4, 32>(sXN, SXN, hW1 + (long)h * DIN * HD2, HD2, DIN,
                          sWORK /*stage into WORK*/, SW1, acc1);
        __syncthreads();
        // raw frags -> sWORK (stride 260)
        #pragma unroll
        for (int mt = 0; mt < 4; mt++)
            #pragma unroll
            for (int nf = 0; nf < 4; nf++) {
                float* a = acc1 + (mt * 4 + nf) * 4;
                int row = mt * 16 + g;
                int col = warp * 32 + nf * 8 + 2 * tig;
                *(float2*)(sWORK + row * SACT + col)       = make_float2(a[0], a[1]);
                *(float2*)(sWORK + (row + 8) * SACT + col) = make_float2(a[2], a[3]);
            }
        __syncthreads();
        // bias + LN + gelu (row-strided), tf32-truncate for next GEMM
        for (int i = 0; i < 8; i++) {
            int r = warp * 8 + i;
            float v[8]; float s = 0.f, ss = 0.f;
            #pragma unroll
            for (int j = 0; j < 8; j++) {
                int c = lane + 32 * j;
                v[j] = sWORK[r * SACT + c] + hb1[h * HD2 + c];
                s += v[j]; ss += v[j] * v[j];
            }
            s = warp_sum(s); ss = warp_sum(ss);
            float mean = s * (1.f / HD2);
            float rstd = rsqrtf(ss * (1.f / HD2) - mean * mean + EPSV);
            #pragma unroll
            for (int j = 0; j < 8; j++) {
                int c = lane + 32 * j;
                float u = (v[j] - mean) * rstd * hln_g[h * HD2 + c] + hln_b[h * HD2 + c];
                sWORK[r * SACT + c] = tf32f(gelu_exact(u));
            }
        }
        __syncthreads();

        // ---- GEMM2: act[64,256] @ hW2[h][256,128] -> state -----------------
        float acc2[32];
        #pragma unroll
        for (int q = 0; q < 32; q++) acc2[q] = 0.f;
        gemm_block<2, 32>(sWORK, SACT, hW2 + (long)h * HD2 * HD, HD, HD2,
                          sWST, SWD, acc2);
        __syncthreads();
        // state + bias -> sWORK stride 132 (fp32, NOT truncated)
        #pragma unroll
        for (int mt = 0; mt < 4; mt++)
            #pragma unroll
            for (int nf = 0; nf < 2; nf++) {
                float* a = acc2 + (mt * 2 + nf) * 4;
                int row = mt * 16 + g;
                int col = warp * 16 + nf * 8 + 2 * tig;
                float2 b = *(const float2*)(hb2 + h * HD + col);
                *(float2*)(sWORK + row * SST + col)       = make_float2(a[0] + b.x, a[1] + b.y);
                *(float2*)(sWORK + (row + 8) * SST + col) = make_float2(a[2] + b.x, a[3] + b.y);
            }
        __syncthreads();

        // ---- dyn GEMM: state[64,128] @ dynamics[h][128,128] ----------------
        float acc3[32];
        #pragma unroll
        for (int q = 0; q < 32; q++) acc3[q] = 0.f;
        gemm_block<2, 32>(sWORK, SST, dynamics + (long)h * HD * HD, HD, HD,
                          sWST, SWD, acc3);
        __syncthreads();
        // raw dy -> sDY stride 132
        #pragma unroll
        for (int mt = 0; mt < 4; mt++)
            #pragma unroll
            for (int nf = 0; nf < 2; nf++) {
                float* a = acc3 + (mt * 2 + nf) * 4;
                int row = mt * 16 + g;
                int col = warp * 16 + nf * 8 + 2 * tig;
                *(float2*)(sDY + row * SST + col)       = make_float2(a[0], a[1]);
                *(float2*)(sDY + (row + 8) * SST + col) = make_float2(a[2], a[3]);
            }
        __syncthreads();

        // ---- glue: attractor softmax + gate + combine -> g_comb -----------
        float att[NAC][4];
        #pragma unroll
        for (int a = 0; a < NAC; a++)
            #pragma unroll
            for (int j = 0; j < 4; j++)
                att[a][j] = attractors[((long)h * NAC + a) * HD + lane + 32 * j];
        float a2v[NAC];
        #pragma unroll
        for (int a = 0; a < NAC; a++) {
            float p = 0.f;
            #pragma unroll
            for (int j = 0; j < 4; j++) p += att[a][j] * att[a][j];
            a2v[a] = warp_sum(p);
        }
        float gwv[16];
        #pragma unroll
        for (int j = 0; j < 16; j++) gwv[j] = gW[h * DIN + lane + 32 * j];

        for (int i = 0; i < 8; i++) {
            int r = warp * 8 + i;
            float st[4], dyv[4];
            #pragma unroll
            for (int j = 0; j < 4; j++) {
                st[j]  = sWORK[r * SST + lane + 32 * j];
                dyv[j] = sDY[r * SST + lane + 32 * j];
            }
            float s2p = 0.f;
            #pragma unroll
            for (int j = 0; j < 4; j++) s2p += st[j] * st[j];
            float s2 = warp_sum(s2p);

            float attn[NAC]; float zmax = -1e30f;
            #pragma unroll
            for (int a = 0; a < NAC; a++) {
                float p = 0.f;
                #pragma unroll
                for (int j = 0; j < 4; j++) p += st[j] * att[a][j];
                p = warp_sum(p);
                float d = sqrtf(fmaxf(s2 + a2v[a] - 2.f * p, 0.f));
                float z = -d * 0.08838834764831845f;
                attn[a] = z; zmax = fmaxf(zmax, z);
            }
            float se = 0.f;
            #pragma unroll
            for (int a = 0; a < NAC; a++) { attn[a] = expf(attn[a] - zmax); se += attn[a]; }
            float inv = 1.f / se;

            float gs = 0.f;
            #pragma unroll
            for (int j = 0; j < 16; j++)
                gs += sXN[r * SXN + lane + 32 * j] * gwv[j];
            gs = warp_sum(gs) + gb[h];
            float gate = 1.f / (1.f + expf(-gs));

            float* cp = g_comb + (t0 + r) * DIN + h * HD;
            #pragma unroll
            for (int j = 0; j < 4; j++) {
                float infl = 0.f;
                #pragma unroll
                for (int a = 0; a < NAC; a++) infl += attn[a] * att[a][j];
                infl *= inv;
                float sv = st[j];
                cp[lane + 32 * j] = sv + gate * 0.1f * (infl - sv + tanhf(dyv[j]));
            }
        }
        // next head's gemm_block starts with __syncthreads()
        __syncthreads();
    }
}

// ---------------------------------------------------------------------------
// K2: comb -> oW1 -> LN/gelu -> oW2 -> xn residual -> out
// ---------------------------------------------------------------------------
__global__ void __launch_bounds__(NTHR, 1)
k2_out(const float* __restrict__ x,
       const float* __restrict__ norm_g, const float* __restrict__ norm_b,
       const float* __restrict__ oW1,    const float* __restrict__ ob1,
       const float* __restrict__ oln_g,  const float* __restrict__ oln_b,
       const float* __restrict__ oW2,    const float* __restrict__ ob2,
       float* __restrict__ out)
{
    float*  sA    = smem + SM2_A;
    float*  sWST  = smem + SM2_WST;
    float2* sStat = (float2*)(smem + SM2_STAT);

    const int tid  = threadIdx.x;
    const int lane = tid & 31;
    const int warp = tid >> 5;
    const int g    = lane >> 2;
    const int tig  = lane & 3;
    const long t0  = (long)blockIdx.x * TM;

    // ---- phase 0: xn stats (fp32) + stage comb tile (tf32) ----------------
    for (int i = 0; i < 8; i++) {
        int r = warp * 8 + i;
        const float* xr = x + (t0 + r) * DIN;
        float s = 0.f, ss = 0.f;
        #pragma unroll
        for (int j = 0; j < 16; j++) {
            float v = xr[lane + 32 * j];
            s += v; ss += v * v;
        }
        s = warp_sum(s); ss = warp_sum(ss);
        float mean = s * (1.f / DIN);
        float rstd = rsqrtf(ss * (1.f / DIN) - mean * mean + EPSV);
        if (lane == 0) sStat[r] = make_float2(mean, rstd);
    }
    for (int idx = tid; idx < TM * (DIN / 4); idx += NTHR) {
        int r = idx >> 7, c = idx & 127;
        float4 v = *(const float4*)(g_comb + (t0 + r) * DIN + c * 4);
        float4 t;
        t.x = tf32f(v.x); t.y = tf32f(v.y); t.z = tf32f(v.z); t.w = tf32f(v.w);
        *(float4*)(sA + r * SO + c * 4) = t;
    }
    __syncthreads();

    // ---- O1 ----------------------------------------------------------------
    float accA[128];
    #pragma unroll
    for (int q = 0; q < 128; q++) accA[q] = 0.f;
    gemm_block<8, 32>(sA, SO, oW1, DIN, DIN, sWST, SWO, accA);
    __syncthreads();
    #pragma unroll
    for (int mt = 0; mt < 4; mt++)
        #pragma unroll
        for (int nf = 0; nf < 8; nf++) {
            float* a = accA + (mt * 8 + nf) * 4;
            int row = mt * 16 + g;
            int col = warp * 64 + nf * 8 + 2 * tig;
            float2 b = *(const float2*)(ob1 + col);
            *(float2*)(sA + row * SO + col)       = make_float2(a[0] + b.x, a[1] + b.y);
            *(float2*)(sA + (row + 8) * SO + col) = make_float2(a[2] + b.x, a[3] + b.y);
        }
    __syncthreads();
    // LN + gelu in place, truncate for O2
    for (int i = 0; i < 8; i++) {
        int r = warp * 8 + i;
        float v[16]; float s = 0.f, ss = 0.f;
        #pragma unroll
        for (int j = 0; j < 16; j++) {
            v[j] = sA[r * SO + lane + 32 * j];
            s += v[j]; ss += v[j] * v[j];
        }
        s = warp_sum(s); ss = warp_sum(ss);
        float mean = s * (1.f / DIN);
        float rstd = rsqrtf(ss * (1.f / DIN) - mean * mean + EPSV);
        #pragma unroll
        for (int j = 0; j < 16; j++) {
            int c = lane + 32 * j;
            float u = (v[j] - mean) * rstd * oln_g[c] + oln_b[c];
            sA[r * SO + c] = tf32f(gelu_exact(u));
        }
    }
    __syncthreads();

    // ---- O2 + fused residual epilogue --------------------------------------
    float accB[128];
    #pragma unroll
    for (int q = 0; q < 128; q++) accB[q] = 0.f;
    gemm_block<8, 32>(sA, SO, oW2, DIN, DIN, sWST, SWO, accB);

    #pragma unroll
    for (int mt = 0; mt < 4; mt++)
        #pragma unroll
        for (int nf = 0; nf < 8; nf++) {
            float* a = accB + (mt * 8 + nf) * 4;
            int col = warp * 64 + nf * 8 + 2 * tig;
            float2 gg = *(const float2*)(norm_g + col);
            float2 bb = *(const float2*)(norm_b + col);
            float2 o2 = *(const float2*)(ob2 + col);
            #pragma unroll
            for (int half = 0; half < 2; half++) {
                int row = mt * 16 + g + 8 * half;
                float2 stt = sStat[row];
                float2 xv = *(const float2*)(x + (t0 + row) * DIN + col);
                float r0 = (xv.x - stt.x) * stt.y * gg.x + bb.x + a[2 * half]     + o2.x;
                float r1 = (xv.y - stt.x) * stt.y * gg.y + bb.y + a[2 * half + 1] + o2.y;
                *(float2*)(out + (t0 + row) * DIN + col) = make_float2(r0, r1);
            }
        }
}

// ---------------------------------------------------------------------------
extern "C" void kernel_launch(void* const* d_in, const int* in_sizes, int n_in,
                              void* d_out, int out_size) {
    (void)in_sizes; (void)n_in; (void)out_size;

    const float* x        = (const float*)d_in[0];
    const float* norm_g   = (const float*)d_in[1];
    const float* norm_b   = (const float*)d_in[2];
    const float* hW1      = (const float*)d_in[3];
    const float* hb1      = (const float*)d_in[4];
    const float* hln_g    = (const float*)d_in[5];
    const float* hln_b    = (const float*)d_in[6];
    const float* hW2      = (const float*)d_in[7];
    const float* hb2      = (const float*)d_in[8];
    const float* attract  = (const float*)d_in[9];
    const float* dynamics = (const float*)d_in[10];
    const float* gW       = (const float*)d_in[11];
    const float* gb       = (const float*)d_in[12];
    const float* oW1      = (const float*)d_in[13];
    const float* ob1      = (const float*)d_in[14];
    const float* oln_g    = (const float*)d_in[15];
    const float* oln_b    = (const float*)d_in[16];
    const float* oW2      = (const float*)d_in[17];
    const float* ob2      = (const float*)d_in[18];
    float* out = (float*)d_out;

    cudaFuncSetAttribute(k1_heads, cudaFuncAttributeMaxDynamicSharedMemorySize, SMEM1_BYTES);
    cudaFuncSetAttribute(k2_out,   cudaFuncAttributeMaxDynamicSharedMemorySize, SMEM2_BYTES);

    k1_heads<<<TOK / TM, NTHR, SMEM1_BYTES>>>(
        x, norm_g, norm_b, hW1, hb1, hln_g, hln_b, hW2, hb2,
        attract, dynamics, gW, gb);
    k2_out<<<TOK / TM, NTHR, SMEM2_BYTES>>>(
        x, norm_g, norm_b, oW1, ob1, oln_g, oln_b, oW2, ob2, out);
}

// round 9
// speedup vs baseline: 1.0022x; 1.0022x over previous
#include <cuda_runtime.h>
#include <math.h>

// ---------------------------------------------------------------------------
// Sizes
// ---------------------------------------------------------------------------
namespace {
constexpr int TOK  = 65536;
constexpr int DIN  = 512;
constexpr int NH   = 4;
constexpr int HD   = 128;
constexpr int HD2  = 256;
constexpr int NAC  = 8;
constexpr int TM   = 64;      // tokens per block
constexpr int NTHR = 256;     // 8 warps
constexpr float EPSV = 1e-5f;

// K1 smem layout (floats). Activation strides == 4 (mod 32); weight-stage
// strides == 8 (mod 32) for conflict-free mma fragment LDS.
constexpr int SXN   = 516;    // xn A operand stride
constexpr int SACT  = 260;    // gemm1 out / gelu act stride
constexpr int SST   = 132;    // state / dy stride
constexpr int SW1   = 264;    // G1 weight stage stride (N=256)
constexpr int SWD   = 136;    // G2/dyn weight stage stride (N=128)
constexpr int SM1_XN   = 0;                     // 64*516 = 33024
constexpr int SM1_WORK = 33024;                 // 16896 floats (aliased uses)
constexpr int SM1_DY   = SM1_WORK + TM * SST;   // dy region = WORK + 8448
constexpr int SM1_WST  = SM1_WORK + 16896;      // 32*136 = 4352
constexpr int SMEM1_FLOATS = SM1_WST + 4352;    // 54272
constexpr int SMEM1_BYTES  = SMEM1_FLOATS * 4;  // 217088

// K2 smem layout
constexpr int SO    = 516;    // A stride
constexpr int SWO   = 520;    // weight stage stride (N=512)
constexpr int SM2_A    = 0;                     // 64*516 = 33024
constexpr int SM2_WST  = 33024;                 // 32*520 = 16640
constexpr int SM2_STAT = SM2_WST + 16640;       // 64 float2 = 128 floats
constexpr int SMEM2_FLOATS = SM2_STAT + 128;    // 49792
constexpr int SMEM2_BYTES  = SMEM2_FLOATS * 4;  // 199168
}

// 128 MB scratch for concatenated head outputs (device global: alloc-free)
__device__ float g_comb[(size_t)TOK * DIN];

// ---------------------------------------------------------------------------
// Helpers
// ---------------------------------------------------------------------------
__device__ __forceinline__ float warp_sum(float v) {
    v += __shfl_xor_sync(0xffffffffu, v, 16);
    v += __shfl_xor_sync(0xffffffffu, v, 8);
    v += __shfl_xor_sync(0xffffffffu, v, 4);
    v += __shfl_xor_sync(0xffffffffu, v, 2);
    v += __shfl_xor_sync(0xffffffffu, v, 1);
    return v;
}

__device__ __forceinline__ float gelu_exact(float u) {
    return 0.5f * u * (1.0f + erff(u * 0.70710678118654752f));
}

// round-to-nearest tf32, returned as float bit pattern
__device__ __forceinline__ float tf32f(float f) {
    unsigned u;
    asm("cvt.rna.tf32.f32 %0, %1;" : "=r"(u) : "f"(f));
    return __uint_as_float(u);
}

__device__ __forceinline__ void mma_tf32(float* c,
                                         unsigned a0, unsigned a1, unsigned a2, unsigned a3,
                                         unsigned b0, unsigned b1) {
    asm volatile(
        "mma.sync.aligned.m16n8k8.row.col.f32.tf32.tf32.f32 "
        "{%0,%1,%2,%3}, {%4,%5,%6,%7}, {%8,%9}, {%0,%1,%2,%3};"
        : "+f"(c[0]), "+f"(c[1]), "+f"(c[2]), "+f"(c[3])
        : "r"(a0), "r"(a1), "r"(a2), "r"(a3), "r"(b0), "r"(b1));
}

// Block-cooperative GEMM: C[64][N] += A[64][K] * W[K][N].
// A in smem (tf32-ready), W staged from global in KT-row tiles (tf32-converted).
// Each warp computes m64 x (NF*8) cols: warp w covers cols [w*NF*8, ...).
// acc layout: acc[(mt*NF + nf)*4 + {0..3}]
template<int NF, int KT>
__device__ __forceinline__ void gemm_block(
    const float* __restrict__ sA, int SA,
    const float* __restrict__ Wg, int N, int K,
    float* __restrict__ sWst, int SW,
    float* __restrict__ acc)
{
    const int tid  = threadIdx.x;
    const int lane = tid & 31;
    const int warp = tid >> 5;
    const int g    = lane >> 2;
    const int tig  = lane & 3;
    const int n0   = warp * (NF * 8);
    const unsigned* uA = (const unsigned*)sA;
    const unsigned* uW = (const unsigned*)sWst;
    const int nf4 = N / 4;

    for (int kt = 0; kt < K; kt += KT) {
        __syncthreads();
        // stage KT x N weight tile, tf32-truncated
        for (int idx = tid; idx < KT * nf4; idx += NTHR) {
            int r = idx / nf4, c = idx % nf4;
            float4 v = *(const float4*)(Wg + (long)(kt + r) * N + c * 4);
            float4 t;
            t.x = tf32f(v.x); t.y = tf32f(v.y); t.z = tf32f(v.z); t.w = tf32f(v.w);
            *(float4*)(sWst + r * SW + c * 4) = t;
        }
        __syncthreads();
        #pragma unroll
        for (int k8 = 0; k8 < KT; k8 += 8) {
            unsigned a[4][4];
            #pragma unroll
            for (int mt = 0; mt < 4; mt++) {
                int rb = mt * 16;
                a[mt][0] = uA[(rb + g)     * SA + kt + k8 + tig];
                a[mt][1] = uA[(rb + g + 8) * SA + kt + k8 + tig];
                a[mt][2] = uA[(rb + g)     * SA + kt + k8 + tig + 4];
                a[mt][3] = uA[(rb + g + 8) * SA + kt + k8 + tig + 4];
            }
            #pragma unroll
            for (int nf = 0; nf < NF; nf++) {
                unsigned b0 = uW[(k8 + tig)     * SW + n0 + nf * 8 + g];
                unsigned b1 = uW[(k8 + tig + 4) * SW + n0 + nf * 8 + g];
                #pragma unroll
                for (int mt = 0; mt < 4; mt++)
                    mma_tf32(acc + (mt * NF + nf) * 4,
                             a[mt][0], a[mt][1], a[mt][2], a[mt][3], b0, b1);
            }
        }
    }
}

extern __shared__ float smem[];

// ---------------------------------------------------------------------------
// K1: LN -> per-head MLP (mma) -> attractor/gate glue -> g_comb
// ---------------------------------------------------------------------------
__global__ void __launch_bounds__(NTHR, 1)
k1_heads(const float* __restrict__ x,
         const float* __restrict__ norm_g, const float* __restrict__ norm_b,
         const float* __restrict__ hW1,    const float* __restrict__ hb1,
         const float* __restrict__ hln_g,  const float* __restrict__ hln_b,
         const float* __restrict__ hW2,    const float* __restrict__ hb2,
         const float* __restrict__ attractors, const float* __restrict__ dynamics,
         const float* __restrict__ gW,     const float* __restrict__ gb)
{
    float* sXN   = smem + SM1_XN;
    float* sWORK = smem + SM1_WORK;   // strides 264 (stage) / 260 (act) / 132 (state)
    float* sDY   = smem + SM1_DY;     // stride 132
    float* sWST  = smem + SM1_WST;

    const int tid  = threadIdx.x;
    const int lane = tid & 31;
    const int warp = tid >> 5;
    const int g    = lane >> 2;
    const int tig  = lane & 3;
    const long t0  = (long)blockIdx.x * TM;

    // ---- phase 0: fp32 LN of x, store tf32-truncated xn -------------------
    for (int i = 0; i < 8; i++) {
        int r = warp * 8 + i;
        const float* xr = x + (t0 + r) * DIN;
        float v[16]; float s = 0.f, ss = 0.f;
        #pragma unroll
        for (int j = 0; j < 16; j++) {
            v[j] = xr[lane + 32 * j];
            s += v[j]; ss += v[j] * v[j];
        }
        s = warp_sum(s); ss = warp_sum(ss);
        float mean = s * (1.f / DIN);
        float rstd = rsqrtf(ss * (1.f / DIN) - mean * mean + EPSV);
        #pragma unroll
        for (int j = 0; j < 16; j++) {
            int c = lane + 32 * j;
            float xn = (v[j] - mean) * rstd * norm_g[c] + norm_b[c];
            sXN[r * SXN + c] = tf32f(xn);
        }
    }
    __syncthreads();

    for (int h = 0; h < NH; h++) {
        // ---- GEMM1: xn[64,512] @ hW1[h][512,256] ---------------------------
        float acc1[64];
        #pragma unroll
        for (int q = 0; q < 64; q++) acc1[q] = 0.f;
        gemm_block<4, 32>(sXN, SXN, hW1 + (long)h * DIN * HD2, HD2, DIN,
                          sWORK /*stage into WORK*/, SW1, acc1);
        __syncthreads();
        // raw frags -> sWORK (stride 260)
        #pragma unroll
        for (int mt = 0; mt < 4; mt++)
            #pragma unroll
            for (int nf = 0; nf < 4; nf++) {
                float* a = acc1 + (mt * 4 + nf) * 4;
                int row = mt * 16 + g;
                int col = warp * 32 + nf * 8 + 2 * tig;
                *(float2*)(sWORK + row * SACT + col)       = make_float2(a[0], a[1]);
                *(float2*)(sWORK + (row + 8) * SACT + col) = make_float2(a[2], a[3]);
            }
        __syncthreads();
        // bias + LN + gelu (row-strided), tf32-truncate for next GEMM
        for (int i = 0; i < 8; i++) {
            int r = warp * 8 + i;
            float v[8]; float s = 0.f, ss = 0.f;
            #pragma unroll
            for (int j = 0; j < 8; j++) {
                int c = lane + 32 * j;
                v[j] = sWORK[r * SACT + c] + hb1[h * HD2 + c];
                s += v[j]; ss += v[j] * v[j];
            }
            s = warp_sum(s); ss = warp_sum(ss);
            float mean = s * (1.f / HD2);
            float rstd = rsqrtf(ss * (1.f / HD2) - mean * mean + EPSV);
            #pragma unroll
            for (int j = 0; j < 8; j++) {
                int c = lane + 32 * j;
                float u = (v[j] - mean) * rstd * hln_g[h * HD2 + c] + hln_b[h * HD2 + c];
                sWORK[r * SACT + c] = tf32f(gelu_exact(u));
            }
        }
        __syncthreads();

        // ---- GEMM2: act[64,256] @ hW2[h][256,128] -> state -----------------
        float acc2[32];
        #pragma unroll
        for (int q = 0; q < 32; q++) acc2[q] = 0.f;
        gemm_block<2, 32>(sWORK, SACT, hW2 + (long)h * HD2 * HD, HD, HD2,
                          sWST, SWD, acc2);
        __syncthreads();
        // state + bias -> sWORK stride 132 (fp32, NOT truncated)
        #pragma unroll
        for (int mt = 0; mt < 4; mt++)
            #pragma unroll
            for (int nf = 0; nf < 2; nf++) {
                float* a = acc2 + (mt * 2 + nf) * 4;
                int row = mt * 16 + g;
                int col = warp * 16 + nf * 8 + 2 * tig;
                float2 b = *(const float2*)(hb2 + h * HD + col);
                *(float2*)(sWORK + row * SST + col)       = make_float2(a[0] + b.x, a[1] + b.y);
                *(float2*)(sWORK + (row + 8) * SST + col) = make_float2(a[2] + b.x, a[3] + b.y);
            }
        __syncthreads();

        // ---- dyn GEMM: state[64,128] @ dynamics[h][128,128] ----------------
        float acc3[32];
        #pragma unroll
        for (int q = 0; q < 32; q++) acc3[q] = 0.f;
        gemm_block<2, 32>(sWORK, SST, dynamics + (long)h * HD * HD, HD, HD,
                          sWST, SWD, acc3);
        __syncthreads();
        // raw dy -> sDY stride 132
        #pragma unroll
        for (int mt = 0; mt < 4; mt++)
            #pragma unroll
            for (int nf = 0; nf < 2; nf++) {
                float* a = acc3 + (mt * 2 + nf) * 4;
                int row = mt * 16 + g;
                int col = warp * 16 + nf * 8 + 2 * tig;
                *(float2*)(sDY + row * SST + col)       = make_float2(a[0], a[1]);
                *(float2*)(sDY + (row + 8) * SST + col) = make_float2(a[2], a[3]);
            }
        __syncthreads();

        // ---- glue: attractor softmax + gate + combine -> g_comb -----------
        float att[NAC][4];
        #pragma unroll
        for (int a = 0; a < NAC; a++)
            #pragma unroll
            for (int j = 0; j < 4; j++)
                att[a][j] = attractors[((long)h * NAC + a) * HD + lane + 32 * j];
        float a2v[NAC];
        #pragma unroll
        for (int a = 0; a < NAC; a++) {
            float p = 0.f;
            #pragma unroll
            for (int j = 0; j < 4; j++) p += att[a][j] * att[a][j];
            a2v[a] = warp_sum(p);
        }
        float gwv[16];
        #pragma unroll
        for (int j = 0; j < 16; j++) gwv[j] = gW[h * DIN + lane + 32 * j];

        for (int i = 0; i < 8; i++) {
            int r = warp * 8 + i;
            float st[4], dyv[4];
            #pragma unroll
            for (int j = 0; j < 4; j++) {
                st[j]  = sWORK[r * SST + lane + 32 * j];
                dyv[j] = sDY[r * SST + lane + 32 * j];
            }
            float s2p = 0.f;
            #pragma unroll
            for (int j = 0; j < 4; j++) s2p += st[j] * st[j];
            float s2 = warp_sum(s2p);

            float attn[NAC]; float zmax = -1e30f;
            #pragma unroll
            for (int a = 0; a < NAC; a++) {
                float p = 0.f;
                #pragma unroll
                for (int j = 0; j < 4; j++) p += st[j] * att[a][j];
                p = warp_sum(p);
                float d = sqrtf(fmaxf(s2 + a2v[a] - 2.f * p, 0.f));
                float z = -d * 0.08838834764831845f;
                attn[a] = z; zmax = fmaxf(zmax, z);
            }
            float se = 0.f;
            #pragma unroll
            for (int a = 0; a < NAC; a++) { attn[a] = expf(attn[a] - zmax); se += attn[a]; }
            float inv = 1.f / se;

            float gs = 0.f;
            #pragma unroll
            for (int j = 0; j < 16; j++)
                gs += sXN[r * SXN + lane + 32 * j] * gwv[j];
            gs = warp_sum(gs) + gb[h];
            float gate = 1.f / (1.f + expf(-gs));

            float* cp = g_comb + (t0 + r) * DIN + h * HD;
            #pragma unroll
            for (int j = 0; j < 4; j++) {
                float infl = 0.f;
                #pragma unroll
                for (int a = 0; a < NAC; a++) infl += attn[a] * att[a][j];
                infl *= inv;
                float sv = st[j];
                cp[lane + 32 * j] = sv + gate * 0.1f * (infl - sv + tanhf(dyv[j]));
            }
        }
        // next head's gemm_block starts with __syncthreads()
        __syncthreads();
    }
}

// ---------------------------------------------------------------------------
// K2: comb -> oW1 -> LN/gelu -> oW2 -> xn residual -> out
// ---------------------------------------------------------------------------
__global__ void __launch_bounds__(NTHR, 1)
k2_out(const float* __restrict__ x,
       const float* __restrict__ norm_g, const float* __restrict__ norm_b,
       const float* __restrict__ oW1,    const float* __restrict__ ob1,
       const float* __restrict__ oln_g,  const float* __restrict__ oln_b,
       const float* __restrict__ oW2,    const float* __restrict__ ob2,
       float* __restrict__ out)
{
    float*  sA    = smem + SM2_A;
    float*  sWST  = smem + SM2_WST;
    float2* sStat = (float2*)(smem + SM2_STAT);

    const int tid  = threadIdx.x;
    const int lane = tid & 31;
    const int warp = tid >> 5;
    const int g    = lane >> 2;
    const int tig  = lane & 3;
    const long t0  = (long)blockIdx.x * TM;

    // ---- phase 0: xn stats (fp32) + stage comb tile (tf32) ----------------
    for (int i = 0; i < 8; i++) {
        int r = warp * 8 + i;
        const float* xr = x + (t0 + r) * DIN;
        float s = 0.f, ss = 0.f;
        #pragma unroll
        for (int j = 0; j < 16; j++) {
            float v = xr[lane + 32 * j];
            s += v; ss += v * v;
        }
        s = warp_sum(s); ss = warp_sum(ss);
        float mean = s * (1.f / DIN);
        float rstd = rsqrtf(ss * (1.f / DIN) - mean * mean + EPSV);
        if (lane == 0) sStat[r] = make_float2(mean, rstd);
    }
    for (int idx = tid; idx < TM * (DIN / 4); idx += NTHR) {
        int r = idx >> 7, c = idx & 127;
        float4 v = *(const float4*)(g_comb + (t0 + r) * DIN + c * 4);
        float4 t;
        t.x = tf32f(v.x); t.y = tf32f(v.y); t.z = tf32f(v.z); t.w = tf32f(v.w);
        *(float4*)(sA + r * SO + c * 4) = t;
    }
    __syncthreads();

    // ---- O1 ----------------------------------------------------------------
    float accA[128];
    #pragma unroll
    for (int q = 0; q < 128; q++) accA[q] = 0.f;
    gemm_block<8, 32>(sA, SO, oW1, DIN, DIN, sWST, SWO, accA);
    __syncthreads();
    #pragma unroll
    for (int mt = 0; mt < 4; mt++)
        #pragma unroll
        for (int nf = 0; nf < 8; nf++) {
            float* a = accA + (mt * 8 + nf) * 4;
            int row = mt * 16 + g;
            int col = warp * 64 + nf * 8 + 2 * tig;
            float2 b = *(const float2*)(ob1 + col);
            *(float2*)(sA + row * SO + col)       = make_float2(a[0] + b.x, a[1] + b.y);
            *(float2*)(sA + (row + 8) * SO + col) = make_float2(a[2] + b.x, a[3] + b.y);
        }
    __syncthreads();
    // LN + gelu in place, truncate for O2
    for (int i = 0; i < 8; i++) {
        int r = warp * 8 + i;
        float v[16]; float s = 0.f, ss = 0.f;
        #pragma unroll
        for (int j = 0; j < 16; j++) {
            v[j] = sA[r * SO + lane + 32 * j];
            s += v[j]; ss += v[j] * v[j];
        }
        s = warp_sum(s); ss = warp_sum(ss);
        float mean = s * (1.f / DIN);
        float rstd = rsqrtf(ss * (1.f / DIN) - mean * mean + EPSV);
        #pragma unroll
        for (int j = 0; j < 16; j++) {
            int c = lane + 32 * j;
            float u = (v[j] - mean) * rstd * oln_g[c] + oln_b[c];
            sA[r * SO + c] = tf32f(gelu_exact(u));
        }
    }
    __syncthreads();

    // ---- O2 + fused residual epilogue --------------------------------------
    float accB[128];
    #pragma unroll
    for (int q = 0; q < 128; q++) accB[q] = 0.f;
    gemm_block<8, 32>(sA, SO, oW2, DIN, DIN, sWST, SWO, accB);

    #pragma unroll
    for (int mt = 0; mt < 4; mt++)
        #pragma unroll
        for (int nf = 0; nf < 8; nf++) {
            float* a = accB + (mt * 8 + nf) * 4;
            int col = warp * 64 + nf * 8 + 2 * tig;
            float2 gg = *(const float2*)(norm_g + col);
            float2 bb = *(const float2*)(norm_b + col);
            float2 o2 = *(const float2*)(ob2 + col);
            #pragma unroll
            for (int half = 0; half < 2; half++) {
                int row = mt * 16 + g + 8 * half;
                float2 stt = sStat[row];
                float2 xv = *(const float2*)(x + (t0 + row) * DIN + col);
                float r0 = (xv.x - stt.x) * stt.y * gg.x + bb.x + a[2 * half]     + o2.x;
                float r1 = (xv.y - stt.x) * stt.y * gg.y + bb.y + a[2 * half + 1] + o2.y;
                *(float2*)(out + (t0 + row) * DIN + col) = make_float2(r0, r1);
            }
        }
}

// ---------------------------------------------------------------------------
extern "C" void kernel_launch(void* const* d_in, const int* in_sizes, int n_in,
                              void* d_out, int out_size) {
    (void)in_sizes; (void)n_in; (void)out_size;

    const float* x        = (const float*)d_in[0];
    const float* norm_g   = (const float*)d_in[1];
    const float* norm_b   = (const float*)d_in[2];
    const float* hW1      = (const float*)d_in[3];
    const float* hb1      = (const float*)d_in[4];
    const float* hln_g    = (const float*)d_in[5];
    const float* hln_b    = (const float*)d_in[6];
    const float* hW2      = (const float*)d_in[7];
    const float* hb2      = (const float*)d_in[8];
    const float* attract  = (const float*)d_in[9];
    const float* dynamics = (const float*)d_in[10];
    const float* gW       = (const float*)d_in[11];
    const float* gb       = (const float*)d_in[12];
    const float* oW1      = (const float*)d_in[13];
    const float* ob1      = (const float*)d_in[14];
    const float* oln_g    = (const float*)d_in[15];
    const float* oln_b    = (const float*)d_in[16];
    const float* oW2      = (const float*)d_in[17];
    const float* ob2      = (const float*)d_in[18];
    float* out = (float*)d_out;

    cudaFuncSetAttribute(k1_heads, cudaFuncAttributeMaxDynamicSharedMemorySize, SMEM1_BYTES);
    cudaFuncSetAttribute(k2_out,   cudaFuncAttributeMaxDynamicSharedMemorySize, SMEM2_BYTES);

    k1_heads<<<TOK / TM, NTHR, SMEM1_BYTES>>>(
        x, norm_g, norm_b, hW1, hb1, hln_g, hln_b, hW2, hb2,
        attract, dynamics, gW, gb);
    k2_out<<<TOK / TM, NTHR, SMEM2_BYTES>>>(
        x, norm_g, norm_b, oW1, ob1, oln_g, oln_b, oW2, ob2, out);
}

// round 10
// speedup vs baseline: 1.0043x; 1.0022x over previous
#include <cuda_runtime.h>
#include <math.h>

// ---------------------------------------------------------------------------
// Sizes
// ---------------------------------------------------------------------------
namespace {
constexpr int TOK  = 65536;
constexpr int DIN  = 512;
constexpr int NH   = 4;
constexpr int HD   = 128;
constexpr int HD2  = 256;
constexpr int NAC  = 8;
constexpr int TM   = 64;      // tokens per block
constexpr int NTHR = 256;     // 8 warps
constexpr float EPSV = 1e-5f;

// K1 smem layout (floats). Activation strides == 4 (mod 32); weight-stage
// strides == 8 (mod 32) for conflict-free mma fragment LDS.
constexpr int SXN   = 516;    // xn A operand stride
constexpr int SACT  = 260;    // gemm1 out / gelu act stride
constexpr int SST   = 132;    // state / dy stride
constexpr int SW1   = 264;    // G1 weight stage stride (N=256)
constexpr int SWD   = 136;    // G2/dyn weight stage stride (N=128)
constexpr int SM1_XN   = 0;                     // 64*516 = 33024
constexpr int SM1_WORK = 33024;                 // 16896 floats (aliased uses)
constexpr int SM1_DY   = SM1_WORK + TM * SST;   // dy region = WORK + 8448
constexpr int SM1_WST  = SM1_WORK + 16896;      // 32*136 = 4352
constexpr int SMEM1_FLOATS = SM1_WST + 4352;    // 54272
constexpr int SMEM1_BYTES  = SMEM1_FLOATS * 4;  // 217088

// K2 smem layout
constexpr int SO    = 516;    // A stride
constexpr int SWO   = 520;    // weight stage stride (N=512)
constexpr int SM2_A    = 0;                     // 64*516 = 33024
constexpr int SM2_WST  = 33024;                 // 32*520 = 16640
constexpr int SM2_STAT = SM2_WST + 16640;       // 64 float2 = 128 floats
constexpr int SMEM2_FLOATS = SM2_STAT + 128;    // 49792
constexpr int SMEM2_BYTES  = SMEM2_FLOATS * 4;  // 199168
}

// 128 MB scratch for concatenated head outputs (device global: alloc-free)
__device__ float g_comb[(size_t)TOK * DIN];

// ---------------------------------------------------------------------------
// Helpers
// ---------------------------------------------------------------------------
__device__ __forceinline__ float warp_sum(float v) {
    v += __shfl_xor_sync(0xffffffffu, v, 16);
    v += __shfl_xor_sync(0xffffffffu, v, 8);
    v += __shfl_xor_sync(0xffffffffu, v, 4);
    v += __shfl_xor_sync(0xffffffffu, v, 2);
    v += __shfl_xor_sync(0xffffffffu, v, 1);
    return v;
}

__device__ __forceinline__ float gelu_exact(float u) {
    return 0.5f * u * (1.0f + erff(u * 0.70710678118654752f));
}

// round-to-nearest tf32, returned as float bit pattern
__device__ __forceinline__ float tf32f(float f) {
    unsigned u;
    asm("cvt.rna.tf32.f32 %0, %1;" : "=r"(u) : "f"(f));
    return __uint_as_float(u);
}

__device__ __forceinline__ void mma_tf32(float* c,
                                         unsigned a0, unsigned a1, unsigned a2, unsigned a3,
                                         unsigned b0, unsigned b1) {
    asm volatile(
        "mma.sync.aligned.m16n8k8.row.col.f32.tf32.tf32.f32 "
        "{%0,%1,%2,%3}, {%4,%5,%6,%7}, {%8,%9}, {%0,%1,%2,%3};"
        : "+f"(c[0]), "+f"(c[1]), "+f"(c[2]), "+f"(c[3])
        : "r"(a0), "r"(a1), "r"(a2), "r"(a3), "r"(b0), "r"(b1));
}

// Block-cooperative GEMM: C[64][N] += A[64][K] * W[K][N].
// A in smem (tf32-ready), W staged from global in KT-row tiles (tf32-converted).
// Each warp computes m64 x (NF*8) cols: warp w covers cols [w*NF*8, ...).
// acc layout: acc[(mt*NF + nf)*4 + {0..3}]
template<int NF, int KT>
__device__ __forceinline__ void gemm_block(
    const float* __restrict__ sA, int SA,
    const float* __restrict__ Wg, int N, int K,
    float* __restrict__ sWst, int SW,
    float* __restrict__ acc)
{
    const int tid  = threadIdx.x;
    const int lane = tid & 31;
    const int warp = tid >> 5;
    const int g    = lane >> 2;
    const int tig  = lane & 3;
    const int n0   = warp * (NF * 8);
    const unsigned* uA = (const unsigned*)sA;
    const unsigned* uW = (const unsigned*)sWst;
    const int nf4 = N / 4;

    for (int kt = 0; kt < K; kt += KT) {
        __syncthreads();
        // stage KT x N weight tile, tf32-truncated
        for (int idx = tid; idx < KT * nf4; idx += NTHR) {
            int r = idx / nf4, c = idx % nf4;
            float4 v = *(const float4*)(Wg + (long)(kt + r) * N + c * 4);
            float4 t;
            t.x = tf32f(v.x); t.y = tf32f(v.y); t.z = tf32f(v.z); t.w = tf32f(v.w);
            *(float4*)(sWst + r * SW + c * 4) = t;
        }
        __syncthreads();
        #pragma unroll
        for (int k8 = 0; k8 < KT; k8 += 8) {
            unsigned a[4][4];
            #pragma unroll
            for (int mt = 0; mt < 4; mt++) {
                int rb = mt * 16;
                a[mt][0] = uA[(rb + g)     * SA + kt + k8 + tig];
                a[mt][1] = uA[(rb + g + 8) * SA + kt + k8 + tig];
                a[mt][2] = uA[(rb + g)     * SA + kt + k8 + tig + 4];
                a[mt][3] = uA[(rb + g + 8) * SA + kt + k8 + tig + 4];
            }
            #pragma unroll
            for (int nf = 0; nf < NF; nf++) {
                unsigned b0 = uW[(k8 + tig)     * SW + n0 + nf * 8 + g];
                unsigned b1 = uW[(k8 + tig + 4) * SW + n0 + nf * 8 + g];
                #pragma unroll
                for (int mt = 0; mt < 4; mt++)
                    mma_tf32(acc + (mt * NF + nf) * 4,
                             a[mt][0], a[mt][1], a[mt][2], a[mt][3], b0, b1);
            }
        }
    }
}

extern __shared__ float smem[];

// ---------------------------------------------------------------------------
// K1: LN -> per-head MLP (mma) -> attractor/gate glue -> g_comb
// ---------------------------------------------------------------------------
__global__ void __launch_bounds__(NTHR, 1)
k1_heads(const float* __restrict__ x,
         const float* __restrict__ norm_g, const float* __restrict__ norm_b,
         const float* __restrict__ hW1,    const float* __restrict__ hb1,
         const float* __restrict__ hln_g,  const float* __restrict__ hln_b,
         const float* __restrict__ hW2,    const float* __restrict__ hb2,
         const float* __restrict__ attractors, const float* __restrict__ dynamics,
         const float* __restrict__ gW,     const float* __restrict__ gb)
{
    float* sXN   = smem + SM1_XN;
    float* sWORK = smem + SM1_WORK;   // strides 264 (stage) / 260 (act) / 132 (state)
    float* sDY   = smem + SM1_DY;     // stride 132
    float* sWST  = smem + SM1_WST;

    const int tid  = threadIdx.x;
    const int lane = tid & 31;
    const int warp = tid >> 5;
    const int g    = lane >> 2;
    const int tig  = lane & 3;
    const long t0  = (long)blockIdx.x * TM;

    // ---- phase 0: fp32 LN of x, store tf32-truncated xn -------------------
    for (int i = 0; i < 8; i++) {
        int r = warp * 8 + i;
        const float* xr = x + (t0 + r) * DIN;
        float v[16]; float s = 0.f, ss = 0.f;
        #pragma unroll
        for (int j = 0; j < 16; j++) {
            v[j] = xr[lane + 32 * j];
            s += v[j]; ss += v[j] * v[j];
        }
        s = warp_sum(s); ss = warp_sum(ss);
        float mean = s * (1.f / DIN);
        float rstd = rsqrtf(ss * (1.f / DIN) - mean * mean + EPSV);
        #pragma unroll
        for (int j = 0; j < 16; j++) {
            int c = lane + 32 * j;
            float xn = (v[j] - mean) * rstd * norm_g[c] + norm_b[c];
            sXN[r * SXN + c] = tf32f(xn);
        }
    }
    __syncthreads();

    for (int h = 0; h < NH; h++) {
        // ---- GEMM1: xn[64,512] @ hW1[h][512,256] ---------------------------
        float acc1[64];
        #pragma unroll
        for (int q = 0; q < 64; q++) acc1[q] = 0.f;
        gemm_block<4, 32>(sXN, SXN, hW1 + (long)h * DIN * HD2, HD2, DIN,
                          sWORK /*stage into WORK*/, SW1, acc1);
        __syncthreads();
        // raw frags -> sWORK (stride 260)
        #pragma unroll
        for (int mt = 0; mt < 4; mt++)
            #pragma unroll
            for (int nf = 0; nf < 4; nf++) {
                float* a = acc1 + (mt * 4 + nf) * 4;
                int row = mt * 16 + g;
                int col = warp * 32 + nf * 8 + 2 * tig;
                *(float2*)(sWORK + row * SACT + col)       = make_float2(a[0], a[1]);
                *(float2*)(sWORK + (row + 8) * SACT + col) = make_float2(a[2], a[3]);
            }
        __syncthreads();
        // bias + LN + gelu (row-strided), tf32-truncate for next GEMM
        for (int i = 0; i < 8; i++) {
            int r = warp * 8 + i;
            float v[8]; float s = 0.f, ss = 0.f;
            #pragma unroll
            for (int j = 0; j < 8; j++) {
                int c = lane + 32 * j;
                v[j] = sWORK[r * SACT + c] + hb1[h * HD2 + c];
                s += v[j]; ss += v[j] * v[j];
            }
            s = warp_sum(s); ss = warp_sum(ss);
            float mean = s * (1.f / HD2);
            float rstd = rsqrtf(ss * (1.f / HD2) - mean * mean + EPSV);
            #pragma unroll
            for (int j = 0; j < 8; j++) {
                int c = lane + 32 * j;
                float u = (v[j] - mean) * rstd * hln_g[h * HD2 + c] + hln_b[h * HD2 + c];
                sWORK[r * SACT + c] = tf32f(gelu_exact(u));
            }
        }
        __syncthreads();

        // ---- GEMM2: act[64,256] @ hW2[h][256,128] -> state -----------------
        float acc2[32];
        #pragma unroll
        for (int q = 0; q < 32; q++) acc2[q] = 0.f;
        gemm_block<2, 32>(sWORK, SACT, hW2 + (long)h * HD2 * HD, HD, HD2,
                          sWST, SWD, acc2);
        __syncthreads();
        // state + bias -> sWORK stride 132 (fp32, NOT truncated)
        #pragma unroll
        for (int mt = 0; mt < 4; mt++)
            #pragma unroll
            for (int nf = 0; nf < 2; nf++) {
                float* a = acc2 + (mt * 2 + nf) * 4;
                int row = mt * 16 + g;
                int col = warp * 16 + nf * 8 + 2 * tig;
                float2 b = *(const float2*)(hb2 + h * HD + col);
                *(float2*)(sWORK + row * SST + col)       = make_float2(a[0] + b.x, a[1] + b.y);
                *(float2*)(sWORK + (row + 8) * SST + col) = make_float2(a[2] + b.x, a[3] + b.y);
            }
        __syncthreads();

        // ---- dyn GEMM: state[64,128] @ dynamics[h][128,128] ----------------
        float acc3[32];
        #pragma unroll
        for (int q = 0; q < 32; q++) acc3[q] = 0.f;
        gemm_block<2, 32>(sWORK, SST, dynamics + (long)h * HD * HD, HD, HD,
                          sWST, SWD, acc3);
        __syncthreads();
        // raw dy -> sDY stride 132
        #pragma unroll
        for (int mt = 0; mt < 4; mt++)
            #pragma unroll
            for (int nf = 0; nf < 2; nf++) {
                float* a = acc3 + (mt * 2 + nf) * 4;
                int row = mt * 16 + g;
                int col = warp * 16 + nf * 8 + 2 * tig;
                *(float2*)(sDY + row * SST + col)       = make_float2(a[0], a[1]);
                *(float2*)(sDY + (row + 8) * SST + col) = make_float2(a[2], a[3]);
            }
        __syncthreads();

        // ---- glue: attractor softmax + gate + combine -> g_comb -----------
        float att[NAC][4];
        #pragma unroll
        for (int a = 0; a < NAC; a++)
            #pragma unroll
            for (int j = 0; j < 4; j++)
                att[a][j] = attractors[((long)h * NAC + a) * HD + lane + 32 * j];
        float a2v[NAC];
        #pragma unroll
        for (int a = 0; a < NAC; a++) {
            float p = 0.f;
            #pragma unroll
            for (int j = 0; j < 4; j++) p += att[a][j] * att[a][j];
            a2v[a] = warp_sum(p);
        }
        float gwv[16];
        #pragma unroll
        for (int j = 0; j < 16; j++) gwv[j] = gW[h * DIN + lane + 32 * j];

        for (int i = 0; i < 8; i++) {
            int r = warp * 8 + i;
            float st[4], dyv[4];
            #pragma unroll
            for (int j = 0; j < 4; j++) {
                st[j]  = sWORK[r * SST + lane + 32 * j];
                dyv[j] = sDY[r * SST + lane + 32 * j];
            }
            float s2p = 0.f;
            #pragma unroll
            for (int j = 0; j < 4; j++) s2p += st[j] * st[j];
            float s2 = warp_sum(s2p);

            float attn[NAC]; float zmax = -1e30f;
            #pragma unroll
            for (int a = 0; a < NAC; a++) {
                float p = 0.f;
                #pragma unroll
                for (int j = 0; j < 4; j++) p += st[j] * att[a][j];
                p = warp_sum(p);
                float d = sqrtf(fmaxf(s2 + a2v[a] - 2.f * p, 0.f));
                float z = -d * 0.08838834764831845f;
                attn[a] = z; zmax = fmaxf(zmax, z);
            }
            float se = 0.f;
            #pragma unroll
            for (int a = 0; a < NAC; a++) { attn[a] = expf(attn[a] - zmax); se += attn[a]; }
            float inv = 1.f / se;

            float gs = 0.f;
            #pragma unroll
            for (int j = 0; j < 16; j++)
                gs += sXN[r * SXN + lane + 32 * j] * gwv[j];
            gs = warp_sum(gs) + gb[h];
            float gate = 1.f / (1.f + expf(-gs));

            float* cp = g_comb + (t0 + r) * DIN + h * HD;
            #pragma unroll
            for (int j = 0; j < 4; j++) {
                float infl = 0.f;
                #pragma unroll
                for (int a = 0; a < NAC; a++) infl += attn[a] * att[a][j];
                infl *= inv;
                float sv = st[j];
                cp[lane + 32 * j] = sv + gate * 0.1f * (infl - sv + tanhf(dyv[j]));
            }
        }
        // next head's gemm_block starts with __syncthreads()
        __syncthreads();
    }
}

// ---------------------------------------------------------------------------
// K2: comb -> oW1 -> LN/gelu -> oW2 -> xn residual -> out
// ---------------------------------------------------------------------------
__global__ void __launch_bounds__(NTHR, 1)
k2_out(const float* __restrict__ x,
       const float* __restrict__ norm_g, const float* __restrict__ norm_b,
       const float* __restrict__ oW1,    const float* __restrict__ ob1,
       const float* __restrict__ oln_g,  const float* __restrict__ oln_b,
       const float* __restrict__ oW2,    const float* __restrict__ ob2,
       float* __restrict__ out)
{
    float*  sA    = smem + SM2_A;
    float*  sWST  = smem + SM2_WST;
    float2* sStat = (float2*)(smem + SM2_STAT);

    const int tid  = threadIdx.x;
    const int lane = tid & 31;
    const int warp = tid >> 5;
    const int g    = lane >> 2;
    const int tig  = lane & 3;
    const long t0  = (long)blockIdx.x * TM;

    // ---- phase 0: xn stats (fp32) + stage comb tile (tf32) ----------------
    for (int i = 0; i < 8; i++) {
        int r = warp * 8 + i;
        const float* xr = x + (t0 + r) * DIN;
        float s = 0.f, ss = 0.f;
        #pragma unroll
        for (int j = 0; j < 16; j++) {
            float v = xr[lane + 32 * j];
            s += v; ss += v * v;
        }
        s = warp_sum(s); ss = warp_sum(ss);
        float mean = s * (1.f / DIN);
        float rstd = rsqrtf(ss * (1.f / DIN) - mean * mean + EPSV);
        if (lane == 0) sStat[r] = make_float2(mean, rstd);
    }
    for (int idx = tid; idx < TM * (DIN / 4); idx += NTHR) {
        int r = idx >> 7, c = idx & 127;
        float4 v = *(const float4*)(g_comb + (t0 + r) * DIN + c * 4);
        float4 t;
        t.x = tf32f(v.x); t.y = tf32f(v.y); t.z = tf32f(v.z); t.w = tf32f(v.w);
        *(float4*)(sA + r * SO + c * 4) = t;
    }
    __syncthreads();

    // ---- O1 ----------------------------------------------------------------
    float accA[128];
    #pragma unroll
    for (int q = 0; q < 128; q++) accA[q] = 0.f;
    gemm_block<8, 32>(sA, SO, oW1, DIN, DIN, sWST, SWO, accA);
    __syncthreads();
    #pragma unroll
    for (int mt = 0; mt < 4; mt++)
        #pragma unroll
        for (int nf = 0; nf < 8; nf++) {
            float* a = accA + (mt * 8 + nf) * 4;
            int row = mt * 16 + g;
            int col = warp * 64 + nf * 8 + 2 * tig;
            float2 b = *(const float2*)(ob1 + col);
            *(float2*)(sA + row * SO + col)       = make_float2(a[0] + b.x, a[1] + b.y);
            *(float2*)(sA + (row + 8) * SO + col) = make_float2(a[2] + b.x, a[3] + b.y);
        }
    __syncthreads();
    // LN + gelu in place, truncate for O2
    for (int i = 0; i < 8; i++) {
        int r = warp * 8 + i;
        float v[16]; float s = 0.f, ss = 0.f;
        #pragma unroll
        for (int j = 0; j < 16; j++) {
            v[j] = sA[r * SO + lane + 32 * j];
            s += v[j]; ss += v[j] * v[j];
        }
        s = warp_sum(s); ss = warp_sum(ss);
        float mean = s * (1.f / DIN);
        float rstd = rsqrtf(ss * (1.f / DIN) - mean * mean + EPSV);
        #pragma unroll
        for (int j = 0; j < 16; j++) {
            int c = lane + 32 * j;
            float u = (v[j] - mean) * rstd * oln_g[c] + oln_b[c];
            sA[r * SO + c] = tf32f(gelu_exact(u));
        }
    }
    __syncthreads();

    // ---- O2 + fused residual epilogue --------------------------------------
    float accB[128];
    #pragma unroll
    for (int q = 0; q < 128; q++) accB[q] = 0.f;
    gemm_block<8, 32>(sA, SO, oW2, DIN, DIN, sWST, SWO, accB);

    #pragma unroll
    for (int mt = 0; mt < 4; mt++)
        #pragma unroll
        for (int nf = 0; nf < 8; nf++) {
            float* a = accB + (mt * 8 + nf) * 4;
            int col = warp * 64 + nf * 8 + 2 * tig;
            float2 gg = *(const float2*)(norm_g + col);
            float2 bb = *(const float2*)(norm_b + col);
            float2 o2 = *(const float2*)(ob2 + col);
            #pragma unroll
            for (int half = 0; half < 2; half++) {
                int row = mt * 16 + g + 8 * half;
                float2 stt = sStat[row];
                float2 xv = *(const float2*)(x + (t0 + row) * DIN + col);
                float r0 = (xv.x - stt.x) * stt.y * gg.x + bb.x + a[2 * half]     + o2.x;
                float r1 = (xv.y - stt.x) * stt.y * gg.y + bb.y + a[2 * half + 1] + o2.y;
                *(float2*)(out + (t0 + row) * DIN + col) = make_float2(r0, r1);
            }
        }
}

// ---------------------------------------------------------------------------
extern "C" void kernel_launch(void* const* d_in, const int* in_sizes, int n_in,
                              void* d_out, int out_size) {
    (void)in_sizes; (void)n_in; (void)out_size;

    const float* x        = (const float*)d_in[0];
    const float* norm_g   = (const float*)d_in[1];
    const float* norm_b   = (const float*)d_in[2];
    const float* hW1      = (const float*)d_in[3];
    const float* hb1      = (const float*)d_in[4];
    const float* hln_g    = (const float*)d_in[5];
    const float* hln_b    = (const float*)d_in[6];
    const float* hW2      = (const float*)d_in[7];
    const float* hb2      = (const float*)d_in[8];
    const float* attract  = (const float*)d_in[9];
    const float* dynamics = (const float*)d_in[10];
    const float* gW       = (const float*)d_in[11];
    const float* gb       = (const float*)d_in[12];
    const float* oW1      = (const float*)d_in[13];
    const float* ob1      = (const float*)d_in[14];
    const float* oln_g    = (const float*)d_in[15];
    const float* oln_b    = (const float*)d_in[16];
    const float* oW2      = (const float*)d_in[17];
    const float* ob2      = (const float*)d_in[18];
    float* out = (float*)d_out;

    cudaFuncSetAttribute(k1_heads, cudaFuncAttributeMaxDynamicSharedMemorySize, SMEM1_BYTES);
    cudaFuncSetAttribute(k2_out,   cudaFuncAttributeMaxDynamicSharedMemorySize, SMEM2_BYTES);

    k1_heads<<<TOK / TM, NTHR, SMEM1_BYTES>>>(
        x, norm_g, norm_b, hW1, hb1, hln_g, hln_b, hW2, hb2,
        attract, dynamics, gW, gb);
    k2_out<<<TOK / TM, NTHR, SMEM2_BYTES>>>(
        x, norm_g, norm_b, oW1, ob1, oln_g, oln_b, oW2, ob2, out);
}

// round 12
// speedup vs baseline: 1.2764x; 1.2709x over previous
#include <cuda_runtime.h>
#include <math.h>

// ---------------------------------------------------------------------------
// Sizes
// ---------------------------------------------------------------------------
namespace {
constexpr int TOK  = 65536;
constexpr int DIN  = 512;
constexpr int NH   = 4;
constexpr int HD   = 128;
constexpr int HD2  = 256;
constexpr int NAC  = 8;
constexpr int TM   = 64;      // tokens per block
constexpr int NTHR = 512;     // 16 warps: 2(M) x 8(N)
constexpr float EPSV = 1e-5f;

// K1 smem layout (floats). Activation strides == 4 (mod 32); weight-stage
// strides == 8 (mod 32) for conflict-free mma fragment LDS.
constexpr int SXN   = 516;    // xn A operand stride
constexpr int SACT  = 260;    // gemm1 out / gelu act stride
constexpr int SST   = 132;    // state / dy stride
constexpr int SW1   = 264;    // G1 weight stage stride (N=256)
constexpr int SWD   = 136;    // G2/dyn weight stage stride (N=128)
constexpr int SM1_XN   = 0;                     // 64*516 = 33024
constexpr int SM1_WORK = 33024;                 // 16896 floats (aliased uses)
constexpr int SM1_DY   = SM1_WORK + TM * SST;   // dy region = WORK + 8448
constexpr int SM1_WST  = SM1_WORK + 16896;      // 2*16*136 = 4352
constexpr int SMEM1_FLOATS = SM1_WST + 4352;    // 54272
constexpr int SMEM1_BYTES  = SMEM1_FLOATS * 4;  // 217088

// K2 smem layout
constexpr int SO    = 516;    // A stride
constexpr int SWO   = 520;    // weight stage stride (N=512)
constexpr int SM2_A    = 0;                     // 64*516 = 33024
constexpr int SM2_WST  = 33024;                 // 2*16*520 = 16640
constexpr int SM2_STAT = SM2_WST + 16640;       // 64 float2 = 128 floats
constexpr int SMEM2_FLOATS = SM2_STAT + 128;    // 49792
constexpr int SMEM2_BYTES  = SMEM2_FLOATS * 4;  // 199168
}

// 128 MB scratch for concatenated head outputs (device global: alloc-free)
__device__ float g_comb[(size_t)TOK * DIN];

// ---------------------------------------------------------------------------
// Helpers
// ---------------------------------------------------------------------------
__device__ __forceinline__ float warp_sum(float v) {
    v += __shfl_xor_sync(0xffffffffu, v, 16);
    v += __shfl_xor_sync(0xffffffffu, v, 8);
    v += __shfl_xor_sync(0xffffffffu, v, 4);
    v += __shfl_xor_sync(0xffffffffu, v, 2);
    v += __shfl_xor_sync(0xffffffffu, v, 1);
    return v;
}

__device__ __forceinline__ float gelu_exact(float u) {
    return 0.5f * u * (1.0f + erff(u * 0.70710678118654752f));
}

// round-to-nearest tf32, returned as float bit pattern
__device__ __forceinline__ float tf32f(float f) {
    unsigned u;
    asm("cvt.rna.tf32.f32 %0, %1;" : "=r"(u) : "f"(f));
    return __uint_as_float(u);
}

__device__ __forceinline__ void mma_tf32(float* c,
                                         unsigned a0, unsigned a1, unsigned a2, unsigned a3,
                                         unsigned b0, unsigned b1) {
    asm volatile(
        "mma.sync.aligned.m16n8k8.row.col.f32.tf32.tf32.f32 "
        "{%0,%1,%2,%3}, {%4,%5,%6,%7}, {%8,%9}, {%0,%1,%2,%3};"
        : "+f"(c[0]), "+f"(c[1]), "+f"(c[2]), "+f"(c[3])
        : "r"(a0), "r"(a1), "r"(a2), "r"(a3), "r"(b0), "r"(b1));
}

// Block-cooperative GEMM with double-buffered weight staging.
// C[64][N] += A[64][K] * W[K][N].  16 warps: wm = warp>>3 (M half, m32),
// wn = warp&7 (N slice of NF*8 cols).  One __syncthreads per K-tile; the
// next tile's LDGs are issued before compute so L2 latency is hidden.
// acc layout: acc[(mt*NF + nf)*4 + {0..3}], mt in {0,1}.
template<int N, int NF, int KT, int K>
__device__ __forceinline__ void gemm_db(
    const float* __restrict__ sA, int SA,
    const float* __restrict__ Wg,
    float* __restrict__ sWst, int SW,
    float* __restrict__ acc)
{
    constexpr int NT  = K / KT;
    constexpr int NF4 = N / 4;
    constexpr int LDR = KT * NF4 / NTHR;   // float4 loads per thread
    const int tid  = threadIdx.x;
    const int lane = tid & 31;
    const int warp = tid >> 5;
    const int g    = lane >> 2;
    const int tig  = lane & 3;
    const int wn   = warp & 7;
    const int wm   = warp >> 3;
    const int n0   = wn * (NF * 8);
    const int m0   = wm * 32;
    const unsigned* uA = (const unsigned*)sA;

    float4 rg[LDR];
    // prologue: stage tile 0
    #pragma unroll
    for (int i = 0; i < LDR; i++) {
        int idx = tid + i * NTHR;
        int r = idx / NF4, c = idx % NF4;
        rg[i] = *(const float4*)(Wg + (long)r * N + c * 4);
    }
    #pragma unroll
    for (int i = 0; i < LDR; i++) {
        int idx = tid + i * NTHR;
        int r = idx / NF4, c = idx % NF4;
        float4 t;
        t.x = tf32f(rg[i].x); t.y = tf32f(rg[i].y);
        t.z = tf32f(rg[i].z); t.w = tf32f(rg[i].w);
        *(float4*)(sWst + r * SW + c * 4) = t;
    }
    __syncthreads();

    for (int t = 0; t < NT; t++) {
        // issue LDGs for tile t+1 (latency overlapped with compute below)
        if (t + 1 < NT) {
            const float* Wt = Wg + (long)(t + 1) * KT * N;
            #pragma unroll
            for (int i = 0; i < LDR; i++) {
                int idx = tid + i * NTHR;
                int r = idx / NF4, c = idx % NF4;
                rg[i] = *(const float4*)(Wt + (long)r * N + c * 4);
            }
        }
        const unsigned* uW = (const unsigned*)(sWst + (t & 1) * KT * SW);
        const int kt = t * KT;
        #pragma unroll
        for (int k8 = 0; k8 < KT; k8 += 8) {
            unsigned a[2][4];
            #pragma unroll
            for (int mt = 0; mt < 2; mt++) {
                int rb = m0 + mt * 16;
                a[mt][0] = uA[(rb + g)     * SA + kt + k8 + tig];
                a[mt][1] = uA[(rb + g + 8) * SA + kt + k8 + tig];
                a[mt][2] = uA[(rb + g)     * SA + kt + k8 + tig + 4];
                a[mt][3] = uA[(rb + g + 8) * SA + kt + k8 + tig + 4];
            }
            #pragma unroll
            for (int nf = 0; nf < NF; nf++) {
                unsigned b0 = uW[(k8 + tig)     * SW + n0 + nf * 8 + g];
                unsigned b1 = uW[(k8 + tig + 4) * SW + n0 + nf * 8 + g];
                #pragma unroll
                for (int mt = 0; mt < 2; mt++)
                    mma_tf32(acc + (mt * NF + nf) * 4,
                             a[mt][0], a[mt][1], a[mt][2], a[mt][3], b0, b1);
            }
        }
        // store tile t+1 into the other buffer
        if (t + 1 < NT) {
            float* dst = sWst + ((t + 1) & 1) * KT * SW;
            #pragma unroll
            for (int i = 0; i < LDR; i++) {
                int idx = tid + i * NTHR;
                int r = idx / NF4, c = idx % NF4;
                float4 v;
                v.x = tf32f(rg[i].x); v.y = tf32f(rg[i].y);
                v.z = tf32f(rg[i].z); v.w = tf32f(rg[i].w);
                *(float4*)(dst + r * SW + c * 4) = v;
            }
        }
        __syncthreads();
    }
}

extern __shared__ float smem[];

// ---------------------------------------------------------------------------
// K1: LN -> per-head MLP (mma) -> attractor/gate glue -> g_comb
// ---------------------------------------------------------------------------
__global__ void __launch_bounds__(NTHR, 1)
k1_heads(const float* __restrict__ x,
         const float* __restrict__ norm_g, const float* __restrict__ norm_b,
         const float* __restrict__ hW1,    const float* __restrict__ hb1,
         const float* __restrict__ hln_g,  const float* __restrict__ hln_b,
         const float* __restrict__ hW2,    const float* __restrict__ hb2,
         const float* __restrict__ attractors, const float* __restrict__ dynamics,
         const float* __restrict__ gW,     const float* __restrict__ gb)
{
    float* sXN   = smem + SM1_XN;
    float* sWORK = smem + SM1_WORK;   // G1 stage (2x16x264) / act 260 / state 132
    float* sDY   = smem + SM1_DY;     // stride 132
    float* sWST  = smem + SM1_WST;    // G2/dyn stage (2x16x136)

    const int tid  = threadIdx.x;
    const int lane = tid & 31;
    const int warp = tid >> 5;
    const int g    = lane >> 2;
    const int tig  = lane & 3;
    const int wn   = warp & 7;
    const int wm   = warp >> 3;
    const int m0   = wm * 32;
    const long t0  = (long)blockIdx.x * TM;

    // ---- phase 0: fp32 LN of x, store tf32-truncated xn -------------------
    #pragma unroll
    for (int i = 0; i < 4; i++) {
        int r = warp * 4 + i;
        const float* xr = x + (t0 + r) * DIN;
        float v[16]; float s = 0.f, ss = 0.f;
        #pragma unroll
        for (int j = 0; j < 16; j++) {
            v[j] = xr[lane + 32 * j];
            s += v[j]; ss += v[j] * v[j];
        }
        s = warp_sum(s); ss = warp_sum(ss);
        float mean = s * (1.f / DIN);
        float rstd = rsqrtf(ss * (1.f / DIN) - mean * mean + EPSV);
        #pragma unroll
        for (int j = 0; j < 16; j++) {
            int c = lane + 32 * j;
            float xn = (v[j] - mean) * rstd * norm_g[c] + norm_b[c];
            sXN[r * SXN + c] = tf32f(xn);
        }
    }
    __syncthreads();

    for (int h = 0; h < NH; h++) {
        // ---- GEMM1: xn[64,512] @ hW1[h][512,256] ---------------------------
        float acc1[32];
        #pragma unroll
        for (int q = 0; q < 32; q++) acc1[q] = 0.f;
        gemm_db<HD2, 4, 16, DIN>(sXN, SXN, hW1 + (long)h * DIN * HD2,
                                 sWORK, SW1, acc1);
        // raw frags -> sWORK (stride 260); region overlaps stage bufs (now free)
        #pragma unroll
        for (int mt = 0; mt < 2; mt++)
            #pragma unroll
            for (int nf = 0; nf < 4; nf++) {
                float* a = acc1 + (mt * 4 + nf) * 4;
                int row = m0 + mt * 16 + g;
                int col = wn * 32 + nf * 8 + 2 * tig;
                *(float2*)(sWORK + row * SACT + col)       = make_float2(a[0], a[1]);
                *(float2*)(sWORK + (row + 8) * SACT + col) = make_float2(a[2], a[3]);
            }
        __syncthreads();
        // bias + LN + gelu (row-strided), tf32-truncate for next GEMM
        #pragma unroll
        for (int i = 0; i < 4; i++) {
            int r = warp * 4 + i;
            float v[8]; float s = 0.f, ss = 0.f;
            #pragma unroll
            for (int j = 0; j < 8; j++) {
                int c = lane + 32 * j;
                v[j] = sWORK[r * SACT + c] + hb1[h * HD2 + c];
                s += v[j]; ss += v[j] * v[j];
            }
            s = warp_sum(s); ss = warp_sum(ss);
            float mean = s * (1.f / HD2);
            float rstd = rsqrtf(ss * (1.f / HD2) - mean * mean + EPSV);
            #pragma unroll
            for (int j = 0; j < 8; j++) {
                int c = lane + 32 * j;
                float u = (v[j] - mean) * rstd * hln_g[h * HD2 + c] + hln_b[h * HD2 + c];
                sWORK[r * SACT + c] = tf32f(gelu_exact(u));
            }
        }
        // gemm_db prologue sync orders these writes before A reads

        // ---- GEMM2: act[64,256] @ hW2[h][256,128] -> state -----------------
        float acc2[16];
        #pragma unroll
        for (int q = 0; q < 16; q++) acc2[q] = 0.f;
        gemm_db<HD, 2, 16, HD2>(sWORK, SACT, hW2 + (long)h * HD2 * HD,
                                sWST, SWD, acc2);
        // state + bias -> sWORK stride 132 (fp32, NOT truncated)
        #pragma unroll
        for (int mt = 0; mt < 2; mt++)
            #pragma unroll
            for (int nf = 0; nf < 2; nf++) {
                float* a = acc2 + (mt * 2 + nf) * 4;
                int row = m0 + mt * 16 + g;
                int col = wn * 16 + nf * 8 + 2 * tig;
                float2 b = *(const float2*)(hb2 + h * HD + col);
                *(float2*)(sWORK + row * SST + col)       = make_float2(a[0] + b.x, a[1] + b.y);
                *(float2*)(sWORK + (row + 8) * SST + col) = make_float2(a[2] + b.x, a[3] + b.y);
            }
        // dyn gemm prologue sync orders these writes before A reads

        // ---- dyn GEMM: state[64,128] @ dynamics[h][128,128] ----------------
        float acc3[16];
        #pragma unroll
        for (int q = 0; q < 16; q++) acc3[q] = 0.f;
        gemm_db<HD, 2, 16, HD>(sWORK, SST, dynamics + (long)h * HD * HD,
                               sWST, SWD, acc3);
        // raw dy -> sDY stride 132
        #pragma unroll
        for (int mt = 0; mt < 2; mt++)
            #pragma unroll
            for (int nf = 0; nf < 2; nf++) {
                float* a = acc3 + (mt * 2 + nf) * 4;
                int row = m0 + mt * 16 + g;
                int col = wn * 16 + nf * 8 + 2 * tig;
                *(float2*)(sDY + row * SST + col)       = make_float2(a[0], a[1]);
                *(float2*)(sDY + (row + 8) * SST + col) = make_float2(a[2], a[3]);
            }
        __syncthreads();

        // ---- glue: attractor softmax + gate + combine -> g_comb -----------
        float att[NAC][4];
        #pragma unroll
        for (int a = 0; a < NAC; a++)
            #pragma unroll
            for (int j = 0; j < 4; j++)
                att[a][j] = attractors[((long)h * NAC + a) * HD + lane + 32 * j];
        float a2v[NAC];
        #pragma unroll
        for (int a = 0; a < NAC; a++) {
            float p = 0.f;
            #pragma unroll
            for (int j = 0; j < 4; j++) p += att[a][j] * att[a][j];
            a2v[a] = warp_sum(p);
        }
        float gwv[16];
        #pragma unroll
        for (int j = 0; j < 16; j++) gwv[j] = gW[h * DIN + lane + 32 * j];

        #pragma unroll
        for (int i = 0; i < 4; i++) {
            int r = warp * 4 + i;
            float st[4], dyv[4];
            #pragma unroll
            for (int j = 0; j < 4; j++) {
                st[j]  = sWORK[r * SST + lane + 32 * j];
                dyv[j] = sDY[r * SST + lane + 32 * j];
            }
            float s2p = 0.f;
            #pragma unroll
            for (int j = 0; j < 4; j++) s2p += st[j] * st[j];
            float s2 = warp_sum(s2p);

            float attn[NAC]; float zmax = -1e30f;
            #pragma unroll
            for (int a = 0; a < NAC; a++) {
                float p = 0.f;
                #pragma unroll
                for (int j = 0; j < 4; j++) p += st[j] * att[a][j];
                p = warp_sum(p);
                float d = sqrtf(fmaxf(s2 + a2v[a] - 2.f * p, 0.f));
                float z = -d * 0.08838834764831845f;
                attn[a] = z; zmax = fmaxf(zmax, z);
            }
            float se = 0.f;
            #pragma unroll
            for (int a = 0; a < NAC; a++) { attn[a] = expf(attn[a] - zmax); se += attn[a]; }
            float inv = 1.f / se;

            float gs = 0.f;
            #pragma unroll
            for (int j = 0; j < 16; j++)
                gs += sXN[r * SXN + lane + 32 * j] * gwv[j];
            gs = warp_sum(gs) + gb[h];
            float gate = 1.f / (1.f + expf(-gs));

            float* cp = g_comb + (t0 + r) * DIN + h * HD;
            #pragma unroll
            for (int j = 0; j < 4; j++) {
                float infl = 0.f;
                #pragma unroll
                for (int a = 0; a < NAC; a++) infl += attn[a] * att[a][j];
                infl *= inv;
                float sv = st[j];
                cp[lane + 32 * j] = sv + gate * 0.1f * (infl - sv + tanhf(dyv[j]));
            }
        }
        // protect state region from next head's G1 prologue STS
        __syncthreads();
    }
}

// ---------------------------------------------------------------------------
// K2: comb -> oW1 -> LN/gelu -> oW2 -> xn residual -> out
// ---------------------------------------------------------------------------
__global__ void __launch_bounds__(NTHR, 1)
k2_out(const float* __restrict__ x,
       const float* __restrict__ norm_g, const float* __restrict__ norm_b,
       const float* __restrict__ oW1,    const float* __restrict__ ob1,
       const float* __restrict__ oln_g,  const float* __restrict__ oln_b,
       const float* __restrict__ oW2,    const float* __restrict__ ob2,
       float* __restrict__ out)
{
    float*  sA    = smem + SM2_A;
    float*  sWST  = smem + SM2_WST;
    float2* sStat = (float2*)(smem + SM2_STAT);

    const int tid  = threadIdx.x;
    const int lane = tid & 31;
    const int warp = tid >> 5;
    const int g    = lane >> 2;
    const int tig  = lane & 3;
    const int wn   = warp & 7;
    const int wm   = warp >> 3;
    const int m0   = wm * 32;
    const long t0  = (long)blockIdx.x * TM;

    // ---- phase 0: xn stats (fp32) + stage comb tile (tf32) ----------------
    #pragma unroll
    for (int i = 0; i < 4; i++) {
        int r = warp * 4 + i;
        const float* xr = x + (t0 + r) * DIN;
        float s = 0.f, ss = 0.f;
        #pragma unroll
        for (int j = 0; j < 16; j++) {
            float v = xr[lane + 32 * j];
            s += v; ss += v * v;
        }
        s = warp_sum(s); ss = warp_sum(ss);
        float mean = s * (1.f / DIN);
        float rstd = rsqrtf(ss * (1.f / DIN) - mean * mean + EPSV);
        if (lane == 0) sStat[r] = make_float2(mean, rstd);
    }
    for (int idx = tid; idx < TM * (DIN / 4); idx += NTHR) {
        int r = idx >> 7, c = idx & 127;
        float4 v = *(const float4*)(g_comb + (t0 + r) * DIN + c * 4);
        float4 t;
        t.x = tf32f(v.x); t.y = tf32f(v.y); t.z = tf32f(v.z); t.w = tf32f(v.w);
        *(float4*)(sA + r * SO + c * 4) = t;
    }
    __syncthreads();

    // ---- O1 ----------------------------------------------------------------
    float accA[64];
    #pragma unroll
    for (int q = 0; q < 64; q++) accA[q] = 0.f;
    gemm_db<DIN, 8, 16, DIN>(sA, SO, oW1, sWST, SWO, accA);
    #pragma unroll
    for (int mt = 0; mt < 2; mt++)
        #pragma unroll
        for (int nf = 0; nf < 8; nf++) {
            float* a = accA + (mt * 8 + nf) * 4;
            int row = m0 + mt * 16 + g;
            int col = wn * 64 + nf * 8 + 2 * tig;
            float2 b = *(const float2*)(ob1 + col);
            *(float2*)(sA + row * SO + col)       = make_float2(a[0] + b.x, a[1] + b.y);
            *(float2*)(sA + (row + 8) * SO + col) = make_float2(a[2] + b.x, a[3] + b.y);
        }
    __syncthreads();
    // LN + gelu in place, truncate for O2
    #pragma unroll
    for (int i = 0; i < 4; i++) {
        int r = warp * 4 + i;
        float v[16]; float s = 0.f, ss = 0.f;
        #pragma unroll
        for (int j = 0; j < 16; j++) {
            v[j] = sA[r * SO + lane + 32 * j];
            s += v[j]; ss += v[j] * v[j];
        }
        s = warp_sum(s); ss = warp_sum(ss);
        float mean = s * (1.f / DIN);
        float rstd = rsqrtf(ss * (1.f / DIN) - mean * mean + EPSV);
        #pragma unroll
        for (int j = 0; j < 16; j++) {
            int c = lane + 32 * j;
            float u = (v[j] - mean) * rstd * oln_g[c] + oln_b[c];
            sA[r * SO + c] = tf32f(gelu_exact(u));
        }
    }
    // O2's prologue sync orders these writes before its A reads

    // ---- O2 + fused residual epilogue --------------------------------------
    float accB[64];
    #pragma unroll
    for (int q = 0; q < 64; q++) accB[q] = 0.f;
    gemm_db<DIN, 8, 16, DIN>(sA, SO, oW2, sWST, SWO, accB);

    #pragma unroll
    for (int mt = 0; mt < 2; mt++)
        #pragma unroll
        for (int nf = 0; nf < 8; nf++) {
            float* a = accB + (mt * 8 + nf) * 4;
            int col = wn * 64 + nf * 8 + 2 * tig;
            float2 gg = *(const float2*)(norm_g + col);
            float2 bb = *(const float2*)(norm_b + col);
            float2 o2 = *(const float2*)(ob2 + col);
            #pragma unroll
            for (int half = 0; half < 2; half++) {
                int row = m0 + mt * 16 + g + 8 * half;
                float2 stt = sStat[row];
                float2 xv = *(const float2*)(x + (t0 + row) * DIN + col);
                float r0 = (xv.x - stt.x) * stt.y * gg.x + bb.x + a[2 * half]     + o2.x;
                float r1 = (xv.y - stt.x) * stt.y * gg.y + bb.y + a[2 * half + 1] + o2.y;
                *(float2*)(out + (t0 + row) * DIN + col) = make_float2(r0, r1);
            }
        }
}

// ---------------------------------------------------------------------------
extern "C" void kernel_launch(void* const* d_in, const int* in_sizes, int n_in,
                              void* d_out, int out_size) {
    (void)in_sizes; (void)n_in; (void)out_size;

    const float* x        = (const float*)d_in[0];
    const float* norm_g   = (const float*)d_in[1];
    const float* norm_b   = (const float*)d_in[2];
    const float* hW1      = (const float*)d_in[3];
    const float* hb1      = (const float*)d_in[4];
    const float* hln_g    = (const float*)d_in[5];
    const float* hln_b    = (const float*)d_in[6];
    const float* hW2      = (const float*)d_in[7];
    const float* hb2      = (const float*)d_in[8];
    const float* attract  = (const float*)d_in[9];
    const float* dynamics = (const float*)d_in[10];
    const float* gW       = (const float*)d_in[11];
    const float* gb       = (const float*)d_in[12];
    const float* oW1      = (const float*)d_in[13];
    const float* ob1      = (const float*)d_in[14];
    const float* oln_g    = (const float*)d_in[15];
    const float* oln_b    = (const float*)d_in[16];
    const float* oW2      = (const float*)d_in[17];
    const float* ob2      = (const float*)d_in[18];
    float* out = (float*)d_out;

    cudaFuncSetAttribute(k1_heads, cudaFuncAttributeMaxDynamicSharedMemorySize, SMEM1_BYTES);
    cudaFuncSetAttribute(k2_out,   cudaFuncAttributeMaxDynamicSharedMemorySize, SMEM2_BYTES);

    k1_heads<<<TOK / TM, NTHR, SMEM1_BYTES>>>(
        x, norm_g, norm_b, hW1, hb1, hln_g, hln_b, hW2, hb2,
        attract, dynamics, gW, gb);
    k2_out<<<TOK / TM, NTHR, SMEM2_BYTES>>>(
        x, norm_g, norm_b, oW1, ob1, oln_g, oln_b, oW2, ob2, out);
}